// round 14
// baseline (speedup 1.0000x reference)
#include <cuda_runtime.h>
#include <cuda_fp16.h>
#include <cstdint>

// Problem constants
#define C_   128
#define H_   120
#define W_   120
#define NB   512
#define DIN  6272     // 128*49
#define H1   512
#define H2   256
#define HW   14400
#define ROWSTRIDE 15360 // 120*128 (HWC row stride in floats)
#define ZS   8
#define KPZ  784      // DIN/ZS
#define NCH  49       // KPZ/16
#define BSCALE 64.0f
#define BSCALE_INV (1.0f / 64.0f)

// Scratch (device globals; allocation is forbidden)
__device__ float g_feat[H_ * W_ * C_];                 // HWC features
__device__ __align__(256) __half g_Ah[NB * DIN];       // roi hi plane
__device__ __align__(256) __half g_Al[NB * DIN];       // roi lo plane
__device__ __align__(256) __half g_Bh[H1 * DIN];       // W1^T fp16 * 64 (single plane)
__device__ float g_h[NB * H1];                         // hidden after relu
__device__ float g_part[2097152];                      // split-K partials

// ============================ PTX helpers ============================
__device__ __forceinline__ uint32_t smem_u32(const void* p) {
    uint32_t a;
    asm("{ .reg .u64 t; cvta.to.shared.u64 t, %1; cvt.u32.u64 %0, t; }" : "=r"(a) : "l"(p));
    return a;
}
#define CPA16(dst, src) \
    asm volatile("cp.async.cg.shared.global [%0], [%1], 16;" :: "r"(dst), "l"(src))
#define CPA_COMMIT() asm volatile("cp.async.commit_group;" ::: "memory")
#define CPA_WAIT1() asm volatile("cp.async.wait_group 1;" ::: "memory")
#define CPA_WAIT0() asm volatile("cp.async.wait_group 0;" ::: "memory")

__device__ __forceinline__ void ldsm4(uint32_t* r, uint32_t addr) {
    asm volatile("ldmatrix.sync.aligned.m8n8.x4.shared.b16 {%0,%1,%2,%3}, [%4];"
                 : "=r"(r[0]), "=r"(r[1]), "=r"(r[2]), "=r"(r[3]) : "r"(addr));
}
__device__ __forceinline__ void mma16816(float* d, const uint32_t* a, const uint32_t* b) {
    asm volatile("mma.sync.aligned.m16n8k16.row.col.f32.f16.f16.f32 "
                 "{%0,%1,%2,%3}, {%4,%5,%6,%7}, {%8,%9}, {%0,%1,%2,%3};"
                 : "+f"(d[0]), "+f"(d[1]), "+f"(d[2]), "+f"(d[3])
                 : "r"(a[0]), "r"(a[1]), "r"(a[2]), "r"(a[3]), "r"(b[0]), "r"(b[1]));
}

// ---------------------------------------------------------------------------
// Kernel A: CHW -> HWC transpose (padded smem, conflict-free)
// ---------------------------------------------------------------------------
__global__ void transpose_kernel(const float* __restrict__ in) {
    __shared__ float tile[30 * 129];
    int y  = blockIdx.x;
    int x0 = blockIdx.y * 30;
    int t  = threadIdx.x;
    for (int i = t; i < 3840; i += 256) {
        int c = i / 30, xx = i % 30;
        tile[xx * 129 + c] = in[c * HW + y * W_ + x0 + xx];
    }
    __syncthreads();
    for (int i = t; i < 3840; i += 256) {
        int xx = i >> 7, c = i & 127;
        g_feat[(y * W_ + x0 + xx) * C_ + c] = tile[xx * 129 + c];
    }
}

// ---------------------------------------------------------------------------
// Kernel B: ROI align with factorized bilinear weights (deduped rows/cols).
// Output fp16 hi/lo planes, k = p*128 + c.
// ---------------------------------------------------------------------------
__global__ void roi_align_kernel(const float* __restrict__ boxes) {
    int n = blockIdx.x;
    __shared__ int   s_nY[7], s_nX[7];
    __shared__ int   s_oY[7][8], s_oX[7][8];
    __shared__ float s_wY[7][8], s_wX[7][8];
    __shared__ float s_inv;

    int t = threadIdx.x;
    if (t < 14) {
        float bx = boxes[n * 4 + 0], by = boxes[n * 4 + 1];
        float bw = boxes[n * 4 + 2], bh = boxes[n * 4 + 3];
        float x1 = bx * 120.0f - 0.5f;
        float y1 = by * 120.0f - 0.5f;
        float rw = bw * 120.0f;
        float rh = bh * 120.0f;
        float binw = rw / 7.0f;
        float binh = rh / 7.0f;
        float gwf = fmaxf(ceilf(rw / 7.0f), 1.0f);
        float ghf = fmaxf(ceilf(rh / 7.0f), 1.0f);
        if (t == 0) s_inv = 1.0f / (ghf * gwf);

        bool isY = (t < 7);
        int  ph  = isY ? t : t - 7;
        int  g   = isY ? (int)ghf : (int)gwf;
        float gf = isY ? ghf : gwf;
        float bin   = isY ? binh : binw;
        float start = isY ? y1 : x1;
        int  stride = isY ? ROWSTRIDE : C_;

        int   offs[8];
        float wts[8];
        int   ne = 0;
        for (int s = 0; s < g; s++) {
            float coord = start + (float)ph * bin + ((float)s + 0.5f) * bin / gf;
            if (coord > -1.0f && coord < 120.0f) {
                float cc  = fminf(fmaxf(coord, 0.0f), 119.0f);
                float c0f = floorf(cc);
                int   c0  = (int)c0f;
                int   c1  = min(c0 + 1, 119);
                float l   = cc - c0f;
                float h   = 1.0f - l;
                int k;
                for (k = 0; k < ne; k++) if (offs[k] == c0) { wts[k] += h; break; }
                if (k == ne) { offs[ne] = c0; wts[ne] = h; ne++; }
                for (k = 0; k < ne; k++) if (offs[k] == c1) { wts[k] += l; break; }
                if (k == ne) { offs[ne] = c1; wts[ne] = l; ne++; }
            }
        }
        if (isY) {
            s_nY[ph] = ne;
            for (int k = 0; k < ne; k++) { s_oY[ph][k] = offs[k] * stride; s_wY[ph][k] = wts[k]; }
        } else {
            s_nX[ph] = ne;
            for (int k = 0; k < ne; k++) { s_oX[ph][k] = offs[k] * stride; s_wX[ph][k] = wts[k]; }
        }
    }
    __syncthreads();

    float inv = s_inv;
    size_t rowoff = (size_t)n * DIN;

    for (int e4 = t; e4 < 1568; e4 += 256) {      // DIN/4
        int p  = e4 >> 5;
        int c4 = (e4 & 31) * 4;
        int ph = p / 7, pw = p % 7;
        int nY = s_nY[ph], nX = s_nX[pw];
        float s0 = 0.f, s1 = 0.f, s2 = 0.f, s3 = 0.f;
        for (int i = 0; i < nY; i++) {
            int   oy = s_oY[ph][i];
            float wy = s_wY[ph][i];
            for (int j = 0; j < nX; j++) {
                float w = wy * s_wX[pw][j];
                float4 f = *(const float4*)&g_feat[oy + s_oX[pw][j] + c4];
                s0 += w * f.x; s1 += w * f.y; s2 += w * f.z; s3 += w * f.w;
            }
        }
        float sv[4] = { s0 * inv, s1 * inv, s2 * inv, s3 * inv };
        uint32_t hB[4], lB[4];
#pragma unroll
        for (int u = 0; u < 4; u++) {
            __half hh = __float2half(sv[u]);
            __half ll = __float2half(sv[u] - __half2float(hh));
            hB[u] = (uint32_t)__half_as_ushort(hh);
            lB[u] = (uint32_t)__half_as_ushort(ll);
        }
        size_t off = rowoff + (size_t)(p * 128 + c4);
        *(uint2*)(g_Ah + off) = make_uint2(hB[0] | (hB[1] << 16), hB[2] | (hB[3] << 16));
        *(uint2*)(g_Al + off) = make_uint2(lB[0] | (lB[1] << 16), lB[2] | (lB[3] << 16));
    }
}

// ---------------------------------------------------------------------------
// Kernel C: W1 [DIN x 512] fp32 -> Bh [512][DIN] fp16 (transposed+permuted)
// Single plane: B[nn][k] = fp16(W1[(k&127)*49 + (k>>7)][nn] * BSCALE)
// ---------------------------------------------------------------------------
__global__ void w1conv_kernel(const float* __restrict__ W1) {
    __shared__ float tile[64][65];
    int k0 = blockIdx.x * 64;
    int n0 = blockIdx.y * 64;
    int t  = threadIdx.x;
    for (int i = t; i < 4096; i += 256) {
        int kk = i >> 6, nn = i & 63;
        int k = k0 + kk;
        int r = (k & 127) * 49 + (k >> 7);
        tile[kk][nn] = W1[(size_t)r * H1 + n0 + nn];
    }
    __syncthreads();
    for (int j = t; j < 1024; j += 256) {
        int kg = j & 15, nn = j >> 4;
        int k4 = kg * 4;
        uint32_t hB[4];
#pragma unroll
        for (int u = 0; u < 4; u++) {
            float v = tile[k4 + u][nn] * BSCALE;
            hB[u] = (uint32_t)__half_as_ushort(__float2half(v));
        }
        size_t off = (size_t)(n0 + nn) * DIN + (size_t)(k0 + k4);
        *(uint2*)(g_Bh + off) = make_uint2(hB[0] | (hB[1] << 16), hB[2] | (hB[3] << 16));
    }
}

// ---------------------------------------------------------------------------
// Kernel D: HMMA GEMM1: part[z] = Ah*Bh + Al*Bh over the z k-slice (2-term).
// BM=128, BN=128, BK=16; grid (4,4,8) = 128 CTAs; 8 warps (2m x 4n, 64x32);
// 3-stage cp.async pipeline, 3 streams (Ah, Al, Bh).
// ---------------------------------------------------------------------------
__global__ void __launch_bounds__(256, 2) gemm1_mma_kernel() {
    __shared__ __align__(16) __half sAh[3][2048];   // 128x16 per stage
    __shared__ __align__(16) __half sAl[3][2048];
    __shared__ __align__(16) __half sBh[3][2048];

    int t = threadIdx.x;
    int lane = t & 31, w = t >> 5;
    int bm = blockIdx.x * 128, bn = blockIdx.y * 128;
    int z = blockIdx.z, k0 = z * KPZ;

    // cp.async mapping: 128 rows x 2 chunks per tile
    int lrow = t >> 1, lc = t & 1;
    int lcs = lc ^ ((lrow >> 2) & 1);
    const __half* gAh = g_Ah + (size_t)(bm + lrow) * DIN + k0 + lc * 8;
    const __half* gAl = g_Al + (size_t)(bm + lrow) * DIN + k0 + lc * 8;
    const __half* gBh = g_Bh + (size_t)(bn + lrow) * DIN + k0 + lc * 8;
    uint32_t doff = (uint32_t)(lrow * 32 + lcs * 16);
    uint32_t dAh = smem_u32(sAh) + doff;
    uint32_t dAl = smem_u32(sAl) + doff;
    uint32_t dBh = smem_u32(sBh) + doff;

    // ldmatrix fragment addresses (within one 4KB stage)
    int mbase = (w >> 2) * 64, nbase = (w & 3) * 32;
    int mat = lane >> 3, lr = lane & 7;
    uint32_t aAddr[4], bAddr[2];
#pragma unroll
    for (int mi = 0; mi < 4; mi++) {
        int r = mbase + mi * 16 + ((mat & 1) << 3) + lr;
        int c = (mat >> 1) ^ ((r >> 2) & 1);
        aAddr[mi] = (uint32_t)(r * 32 + c * 16);
    }
#pragma unroll
    for (int nb = 0; nb < 2; nb++) {
        int r = nbase + nb * 16 + ((mat >> 1) << 3) + lr;
        int c = (mat & 1) ^ ((r >> 2) & 1);
        bAddr[nb] = (uint32_t)(r * 32 + c * 16);
    }
    uint32_t bA_h = smem_u32(sAh), bA_l = smem_u32(sAl);
    uint32_t bB_h = smem_u32(sBh);

    float acc[4][4][4];
#pragma unroll
    for (int i = 0; i < 4; i++)
#pragma unroll
        for (int j = 0; j < 4; j++)
#pragma unroll
            for (int q = 0; q < 4; q++) acc[i][j][q] = 0.0f;

    // prefetch chunks 0,1 into stages 0,1
#pragma unroll
    for (int pc = 0; pc < 2; pc++) {
        uint32_t so = (uint32_t)(pc * 4096);
        size_t ko = (size_t)pc * 16;
        CPA16(dAh + so, gAh + ko); CPA16(dAl + so, gAl + ko);
        CPA16(dBh + so, gBh + ko);
        CPA_COMMIT();
    }

    for (int ch = 0; ch < NCH; ch++) {
        if (ch < NCH - 1) { CPA_WAIT1(); } else { CPA_WAIT0(); }
        __syncthreads();
        if (ch + 2 < NCH) {
            int st2 = (ch + 2) % 3;
            uint32_t so = (uint32_t)(st2 * 4096);
            size_t ko = (size_t)(ch + 2) * 16;
            CPA16(dAh + so, gAh + ko); CPA16(dAl + so, gAl + ko);
            CPA16(dBh + so, gBh + ko);
            CPA_COMMIT();
        }
        int st = ch % 3;
        uint32_t so = (uint32_t)(st * 4096);

        uint32_t ah[4][4], al[4][4], bb[2][4];
#pragma unroll
        for (int mi = 0; mi < 4; mi++) {
            ldsm4(ah[mi], bA_h + so + aAddr[mi]);
            ldsm4(al[mi], bA_l + so + aAddr[mi]);
        }
#pragma unroll
        for (int nb = 0; nb < 2; nb++) ldsm4(bb[nb], bB_h + so + bAddr[nb]);
        // pass 1: Ah*Bh — 16 independent accumulators
#pragma unroll
        for (int mi = 0; mi < 4; mi++)
#pragma unroll
            for (int ni = 0; ni < 4; ni++)
                mma16816(acc[mi][ni], ah[mi], &bb[ni >> 1][(ni & 1) * 2]);
        // pass 2: Al*Bh
#pragma unroll
        for (int mi = 0; mi < 4; mi++)
#pragma unroll
            for (int ni = 0; ni < 4; ni++)
                mma16816(acc[mi][ni], al[mi], &bb[ni >> 1][(ni & 1) * 2]);
    }

    float* pz = g_part + (size_t)z * (NB * H1);
    int r0 = lane >> 2, cc0 = (lane & 3) * 2;
#pragma unroll
    for (int mi = 0; mi < 4; mi++)
#pragma unroll
        for (int ni = 0; ni < 4; ni++) {
            int m = bm + mbase + mi * 16 + r0;
            int nn = bn + nbase + ni * 8 + cc0;
            *(float2*)&pz[(size_t)m * H1 + nn] =
                make_float2(acc[mi][ni][0], acc[mi][ni][1]);
            *(float2*)&pz[(size_t)(m + 8) * H1 + nn] =
                make_float2(acc[mi][ni][2], acc[mi][ni][3]);
        }
}

// ---------------------------------------------------------------------------
// SIMT split-K SGEMM for GEMM2 (double-buffered)
// ---------------------------------------------------------------------------
template <int M, int N, int K, int KPS>
__device__ __forceinline__ void sgemm_body(const float* __restrict__ A,
                                           const float* __restrict__ B,
                                           float* __restrict__ part) {
    __shared__ float As[2][8][128];
    __shared__ float Bs[2][8][128];
    int bm = blockIdx.x * 128;
    int bn = blockIdx.y * 128;
    int z  = blockIdx.z;
    int k0 = z * KPS;
    int t  = threadIdx.x;
    int tx = t & 15;
    int ty = t >> 4;
    int arow  = t >> 1;
    int acol4 = (t & 1) * 4;
    int brow  = t >> 5;
    int bcol4 = (t & 31) * 4;

    const float* aptr = &A[(size_t)(bm + arow) * K + k0 + acol4];
    float acc[8][8];
#pragma unroll
    for (int i = 0; i < 8; i++)
#pragma unroll
        for (int j = 0; j < 8; j++) acc[i][j] = 0.0f;

    float4 av = *(const float4*)(aptr);
    float4 bv = *(const float4*)&B[(size_t)(k0 + brow) * N + bn + bcol4];
    int cur = 0;
    As[0][acol4 + 0][arow] = av.x;
    As[0][acol4 + 1][arow] = av.y;
    As[0][acol4 + 2][arow] = av.z;
    As[0][acol4 + 3][arow] = av.w;
    *(float4*)&Bs[0][brow][bcol4] = bv;
    __syncthreads();

    for (int kt = 0; kt < KPS; kt += 8) {
        bool has_next = (kt + 8) < KPS;
        if (has_next) {
            av = *(const float4*)(aptr + kt + 8);
            bv = *(const float4*)&B[(size_t)(k0 + kt + 8 + brow) * N + bn + bcol4];
        }
#pragma unroll
        for (int kr = 0; kr < 8; kr++) {
            float a[8], b[8];
            *(float4*)&a[0] = *(const float4*)&As[cur][kr][ty * 8];
            *(float4*)&a[4] = *(const float4*)&As[cur][kr][ty * 8 + 4];
            *(float4*)&b[0] = *(const float4*)&Bs[cur][kr][tx * 8];
            *(float4*)&b[4] = *(const float4*)&Bs[cur][kr][tx * 8 + 4];
#pragma unroll
            for (int i = 0; i < 8; i++)
#pragma unroll
                for (int j = 0; j < 8; j++) acc[i][j] += a[i] * b[j];
        }
        if (has_next) {
            int nxt = cur ^ 1;
            As[nxt][acol4 + 0][arow] = av.x;
            As[nxt][acol4 + 1][arow] = av.y;
            As[nxt][acol4 + 2][arow] = av.z;
            As[nxt][acol4 + 3][arow] = av.w;
            *(float4*)&Bs[nxt][brow][bcol4] = bv;
            __syncthreads();
            cur = nxt;
        }
    }
    float* p = part + (size_t)z * M * N;
#pragma unroll
    for (int i = 0; i < 8; i++) {
        int m = bm + ty * 8 + i;
#pragma unroll
        for (int j = 0; j < 8; j += 4) {
            float4 v = make_float4(acc[i][j], acc[i][j + 1], acc[i][j + 2], acc[i][j + 3]);
            *(float4*)&p[(size_t)m * N + bn + tx * 8 + j] = v;
        }
    }
}

__global__ void __launch_bounds__(256) gemm2_kernel(const float* __restrict__ W2) {
    sgemm_body<NB, H2, H1, 32>(g_h, W2, g_part);
}

// Reduce split-K partials + bias (+relu for layer 1)
__global__ void reduce1_kernel(const float* __restrict__ b1) {
    int i = (blockIdx.x * 256 + threadIdx.x) * 4;
    float4 s = make_float4(0.f, 0.f, 0.f, 0.f);
#pragma unroll
    for (int z = 0; z < ZS; z++) {
        float4 v = *(const float4*)&g_part[(size_t)z * (NB * H1) + i];
        s.x += v.x; s.y += v.y; s.z += v.z; s.w += v.w;
    }
    int bi = i & (H1 - 1);
    s.x = fmaxf(s.x * BSCALE_INV + b1[bi + 0], 0.f);
    s.y = fmaxf(s.y * BSCALE_INV + b1[bi + 1], 0.f);
    s.z = fmaxf(s.z * BSCALE_INV + b1[bi + 2], 0.f);
    s.w = fmaxf(s.w * BSCALE_INV + b1[bi + 3], 0.f);
    *(float4*)&g_h[i] = s;
}

__global__ void reduce2_kernel(const float* __restrict__ b2, float* __restrict__ out) {
    int i = (blockIdx.x * 256 + threadIdx.x) * 4;
    float4 s = make_float4(0.f, 0.f, 0.f, 0.f);
#pragma unroll
    for (int z = 0; z < 16; z++) {
        float4 v = *(const float4*)&g_part[(size_t)z * (NB * H2) + i];
        s.x += v.x; s.y += v.y; s.z += v.z; s.w += v.w;
    }
    int bi = i & (H2 - 1);
    s.x += b2[bi + 0]; s.y += b2[bi + 1]; s.z += b2[bi + 2]; s.w += b2[bi + 3];
    *(float4*)&out[i] = s;
}

// ---------------------------------------------------------------------------
extern "C" void kernel_launch(void* const* d_in, const int* in_sizes, int n_in,
                              void* d_out, int out_size) {
    const float* features = (const float*)d_in[0];
    const float* boxes    = (const float*)d_in[1];
    const float* W1       = (const float*)d_in[2];
    const float* b1       = (const float*)d_in[3];
    const float* W2       = (const float*)d_in[4];
    const float* b2       = (const float*)d_in[5];
    float* out            = (float*)d_out;

    transpose_kernel<<<dim3(120, 4), 256>>>(features);
    roi_align_kernel<<<NB, 256>>>(boxes);
    w1conv_kernel<<<dim3(98, 8), 256>>>(W1);
    gemm1_mma_kernel<<<dim3(4, 4, ZS), 256>>>();
    reduce1_kernel<<<256, 256>>>(b1);
    gemm2_kernel<<<dim3(4, 2, 16), 256>>>(W2);
    reduce2_kernel<<<128, 256>>>(b2, out);
}

// round 17
// speedup vs baseline: 1.5559x; 1.5559x over previous
#include <cuda_runtime.h>
#include <cuda_fp16.h>
#include <cstdint>

// Problem constants
#define C_   128
#define H_   120
#define W_   120
#define NB   512
#define DIN  6272     // 128*49
#define H1   512
#define H2   256
#define HW   14400
#define ROWSTRIDE 15360 // 120*128 (HWC row stride in floats)
#define ZS   8
#define KPZ  784      // DIN/ZS
#define NCH  49       // KPZ/16
#define NIT  25       // 24 pairs + 1 tail chunk
#define BSCALE 64.0f
#define BSCALE_INV (1.0f / 64.0f)

// Scratch (device globals; allocation is forbidden)
__device__ float g_feat[H_ * W_ * C_];                 // HWC features
__device__ __align__(256) __half g_Ah[NB * DIN];       // roi hi plane
__device__ __align__(256) __half g_Al[NB * DIN];       // roi lo plane
__device__ __align__(256) __half g_Bh[H1 * DIN];       // W1^T fp16 * 64 (single plane)
__device__ float g_h[NB * H1];                         // hidden after relu
__device__ float g_part[2097152];                      // split-K partials

// ============================ PTX helpers ============================
__device__ __forceinline__ uint32_t smem_u32(const void* p) {
    uint32_t a;
    asm("{ .reg .u64 t; cvta.to.shared.u64 t, %1; cvt.u32.u64 %0, t; }" : "=r"(a) : "l"(p));
    return a;
}
#define CPA16(dst, src) \
    asm volatile("cp.async.cg.shared.global [%0], [%1], 16;" :: "r"(dst), "l"(src))
#define CPA_COMMIT() asm volatile("cp.async.commit_group;" ::: "memory")
#define CPA_WAIT0() asm volatile("cp.async.wait_group 0;" ::: "memory")

__device__ __forceinline__ void ldsm4(uint32_t* r, uint32_t addr) {
    asm volatile("ldmatrix.sync.aligned.m8n8.x4.shared.b16 {%0,%1,%2,%3}, [%4];"
                 : "=r"(r[0]), "=r"(r[1]), "=r"(r[2]), "=r"(r[3]) : "r"(addr));
}
__device__ __forceinline__ void mma16816(float* d, const uint32_t* a, const uint32_t* b) {
    asm volatile("mma.sync.aligned.m16n8k16.row.col.f32.f16.f16.f32 "
                 "{%0,%1,%2,%3}, {%4,%5,%6,%7}, {%8,%9}, {%0,%1,%2,%3};"
                 : "+f"(d[0]), "+f"(d[1]), "+f"(d[2]), "+f"(d[3])
                 : "r"(a[0]), "r"(a[1]), "r"(a[2]), "r"(a[3]), "r"(b[0]), "r"(b[1]));
}

// ---------------------------------------------------------------------------
// Kernel A: CHW -> HWC transpose (padded smem, conflict-free)
// ---------------------------------------------------------------------------
__global__ void transpose_kernel(const float* __restrict__ in) {
    __shared__ float tile[30 * 129];
    int y  = blockIdx.x;
    int x0 = blockIdx.y * 30;
    int t  = threadIdx.x;
    for (int i = t; i < 3840; i += 256) {
        int c = i / 30, xx = i % 30;
        tile[xx * 129 + c] = in[c * HW + y * W_ + x0 + xx];
    }
    __syncthreads();
    for (int i = t; i < 3840; i += 256) {
        int xx = i >> 7, c = i & 127;
        g_feat[(y * W_ + x0 + xx) * C_ + c] = tile[xx * 129 + c];
    }
}

// ---------------------------------------------------------------------------
// Kernel B: ROI align with factorized bilinear weights (deduped rows/cols).
// Output fp16 hi/lo planes, k = p*128 + c.
// ---------------------------------------------------------------------------
__global__ void roi_align_kernel(const float* __restrict__ boxes) {
    int n = blockIdx.x;
    __shared__ int   s_nY[7], s_nX[7];
    __shared__ int   s_oY[7][8], s_oX[7][8];
    __shared__ float s_wY[7][8], s_wX[7][8];
    __shared__ float s_inv;

    int t = threadIdx.x;
    if (t < 14) {
        float bx = boxes[n * 4 + 0], by = boxes[n * 4 + 1];
        float bw = boxes[n * 4 + 2], bh = boxes[n * 4 + 3];
        float x1 = bx * 120.0f - 0.5f;
        float y1 = by * 120.0f - 0.5f;
        float rw = bw * 120.0f;
        float rh = bh * 120.0f;
        float binw = rw / 7.0f;
        float binh = rh / 7.0f;
        float gwf = fmaxf(ceilf(rw / 7.0f), 1.0f);
        float ghf = fmaxf(ceilf(rh / 7.0f), 1.0f);
        if (t == 0) s_inv = 1.0f / (ghf * gwf);

        bool isY = (t < 7);
        int  ph  = isY ? t : t - 7;
        int  g   = isY ? (int)ghf : (int)gwf;
        float gf = isY ? ghf : gwf;
        float bin   = isY ? binh : binw;
        float start = isY ? y1 : x1;
        int  stride = isY ? ROWSTRIDE : C_;

        int   offs[8];
        float wts[8];
        int   ne = 0;
        for (int s = 0; s < g; s++) {
            float coord = start + (float)ph * bin + ((float)s + 0.5f) * bin / gf;
            if (coord > -1.0f && coord < 120.0f) {
                float cc  = fminf(fmaxf(coord, 0.0f), 119.0f);
                float c0f = floorf(cc);
                int   c0  = (int)c0f;
                int   c1  = min(c0 + 1, 119);
                float l   = cc - c0f;
                float h   = 1.0f - l;
                int k;
                for (k = 0; k < ne; k++) if (offs[k] == c0) { wts[k] += h; break; }
                if (k == ne) { offs[ne] = c0; wts[ne] = h; ne++; }
                for (k = 0; k < ne; k++) if (offs[k] == c1) { wts[k] += l; break; }
                if (k == ne) { offs[ne] = c1; wts[ne] = l; ne++; }
            }
        }
        if (isY) {
            s_nY[ph] = ne;
            for (int k = 0; k < ne; k++) { s_oY[ph][k] = offs[k] * stride; s_wY[ph][k] = wts[k]; }
        } else {
            s_nX[ph] = ne;
            for (int k = 0; k < ne; k++) { s_oX[ph][k] = offs[k] * stride; s_wX[ph][k] = wts[k]; }
        }
    }
    __syncthreads();

    float inv = s_inv;
    size_t rowoff = (size_t)n * DIN;

    for (int e4 = t; e4 < 1568; e4 += 256) {      // DIN/4
        int p  = e4 >> 5;
        int c4 = (e4 & 31) * 4;
        int ph = p / 7, pw = p % 7;
        int nY = s_nY[ph], nX = s_nX[pw];
        float s0 = 0.f, s1 = 0.f, s2 = 0.f, s3 = 0.f;
        for (int i = 0; i < nY; i++) {
            int   oy = s_oY[ph][i];
            float wy = s_wY[ph][i];
            for (int j = 0; j < nX; j++) {
                float w = wy * s_wX[pw][j];
                float4 f = *(const float4*)&g_feat[oy + s_oX[pw][j] + c4];
                s0 += w * f.x; s1 += w * f.y; s2 += w * f.z; s3 += w * f.w;
            }
        }
        float sv[4] = { s0 * inv, s1 * inv, s2 * inv, s3 * inv };
        uint32_t hB[4], lB[4];
#pragma unroll
        for (int u = 0; u < 4; u++) {
            __half hh = __float2half(sv[u]);
            __half ll = __float2half(sv[u] - __half2float(hh));
            hB[u] = (uint32_t)__half_as_ushort(hh);
            lB[u] = (uint32_t)__half_as_ushort(ll);
        }
        size_t off = rowoff + (size_t)(p * 128 + c4);
        *(uint2*)(g_Ah + off) = make_uint2(hB[0] | (hB[1] << 16), hB[2] | (hB[3] << 16));
        *(uint2*)(g_Al + off) = make_uint2(lB[0] | (lB[1] << 16), lB[2] | (lB[3] << 16));
    }
}

// ---------------------------------------------------------------------------
// Kernel C: W1 [DIN x 512] fp32 -> Bh [512][DIN] fp16 (transposed+permuted)
// ---------------------------------------------------------------------------
__global__ void w1conv_kernel(const float* __restrict__ W1) {
    __shared__ float tile[64][65];
    int k0 = blockIdx.x * 64;
    int n0 = blockIdx.y * 64;
    int t  = threadIdx.x;
    for (int i = t; i < 4096; i += 256) {
        int kk = i >> 6, nn = i & 63;
        int k = k0 + kk;
        int r = (k & 127) * 49 + (k >> 7);
        tile[kk][nn] = W1[(size_t)r * H1 + n0 + nn];
    }
    __syncthreads();
    for (int j = t; j < 1024; j += 256) {
        int kg = j & 15, nn = j >> 4;
        int k4 = kg * 4;
        uint32_t hB[4];
#pragma unroll
        for (int u = 0; u < 4; u++) {
            float v = tile[k4 + u][nn] * BSCALE;
            hB[u] = (uint32_t)__half_as_ushort(__float2half(v));
        }
        size_t off = (size_t)(n0 + nn) * DIN + (size_t)(k0 + k4);
        *(uint2*)(g_Bh + off) = make_uint2(hB[0] | (hB[1] << 16), hB[2] | (hB[3] << 16));
    }
}

// ---------------------------------------------------------------------------
// Kernel D: HMMA GEMM1 (2-term): part[z] = Ah*Bh + Al*Bh over the z k-slice.
// BM=128, BN=128; grid (4,4,8) = 128 CTAs; 8 warps (2m x 4n, 64x32 tiles).
// TWO chunks per iteration: 25 iterations instead of 49 — halves the number
// of barrier/wait boundaries (the empirically fixed per-iteration cost).
// 4-stage ring (stage = chunk & 3), 3 streams x 4 x 4KB = 48KB smem.
// ---------------------------------------------------------------------------
__global__ void __launch_bounds__(256, 2) gemm1_mma_kernel() {
    __shared__ __align__(16) __half sAh[4][2048];   // 128x16 per stage
    __shared__ __align__(16) __half sAl[4][2048];
    __shared__ __align__(16) __half sBh[4][2048];

    int t = threadIdx.x;
    int lane = t & 31, w = t >> 5;
    int bm = blockIdx.x * 128, bn = blockIdx.y * 128;
    int z = blockIdx.z, k0 = z * KPZ;

    // cp.async mapping: 128 rows x 2 chunks per tile
    int lrow = t >> 1, lc = t & 1;
    int lcs = lc ^ ((lrow >> 2) & 1);
    const __half* gAh = g_Ah + (size_t)(bm + lrow) * DIN + k0 + lc * 8;
    const __half* gAl = g_Al + (size_t)(bm + lrow) * DIN + k0 + lc * 8;
    const __half* gBh = g_Bh + (size_t)(bn + lrow) * DIN + k0 + lc * 8;
    uint32_t doff = (uint32_t)(lrow * 32 + lcs * 16);
    uint32_t dAh = smem_u32(sAh) + doff;
    uint32_t dAl = smem_u32(sAl) + doff;
    uint32_t dBh = smem_u32(sBh) + doff;

    // ldmatrix fragment addresses (within one 4KB stage)
    int mbase = (w >> 2) * 64, nbase = (w & 3) * 32;
    int mat = lane >> 3, lr = lane & 7;
    uint32_t aAddr[4], bAddr[2];
#pragma unroll
    for (int mi = 0; mi < 4; mi++) {
        int r = mbase + mi * 16 + ((mat & 1) << 3) + lr;
        int c = (mat >> 1) ^ ((r >> 2) & 1);
        aAddr[mi] = (uint32_t)(r * 32 + c * 16);
    }
#pragma unroll
    for (int nb = 0; nb < 2; nb++) {
        int r = nbase + nb * 16 + ((mat >> 1) << 3) + lr;
        int c = (mat & 1) ^ ((r >> 2) & 1);
        bAddr[nb] = (uint32_t)(r * 32 + c * 16);
    }
    uint32_t bA_h = smem_u32(sAh), bA_l = smem_u32(sAl);
    uint32_t bB_h = smem_u32(sBh);

    float acc[4][4][4];
#pragma unroll
    for (int i = 0; i < 4; i++)
#pragma unroll
        for (int j = 0; j < 4; j++)
#pragma unroll
            for (int q = 0; q < 4; q++) acc[i][j][q] = 0.0f;

    auto prefetch = [&](int ch) {
        uint32_t so = (uint32_t)((ch & 3) * 4096);
        size_t ko = (size_t)ch * 16;
        CPA16(dAh + so, gAh + ko);
        CPA16(dAl + so, gAl + ko);
        CPA16(dBh + so, gBh + ko);
    };
    auto compute_chunk = [&](int ch) {
        uint32_t so = (uint32_t)((ch & 3) * 4096);
        uint32_t ah[4][4], al[4][4], bb[2][4];
#pragma unroll
        for (int mi = 0; mi < 4; mi++) {
            ldsm4(ah[mi], bA_h + so + aAddr[mi]);
            ldsm4(al[mi], bA_l + so + aAddr[mi]);
        }
#pragma unroll
        for (int nb = 0; nb < 2; nb++) ldsm4(bb[nb], bB_h + so + bAddr[nb]);
#pragma unroll
        for (int mi = 0; mi < 4; mi++)
#pragma unroll
            for (int ni = 0; ni < 4; ni++)
                mma16816(acc[mi][ni], ah[mi], &bb[ni >> 1][(ni & 1) * 2]);
#pragma unroll
        for (int mi = 0; mi < 4; mi++)
#pragma unroll
            for (int ni = 0; ni < 4; ni++)
                mma16816(acc[mi][ni], al[mi], &bb[ni >> 1][(ni & 1) * 2]);
    };

    // prologue: iteration 0 = chunks 0,1
    prefetch(0); prefetch(1); CPA_COMMIT();

    for (int it = 0; it < NIT; it++) {
        CPA_WAIT0();
        __syncthreads();
        if (it + 1 < NIT) {
            int c0 = 2 * (it + 1);
            prefetch(c0);
            if (c0 + 1 < NCH) prefetch(c0 + 1);
            CPA_COMMIT();
        }
        int base = 2 * it;
        compute_chunk(base);
        if (base + 1 < NCH) compute_chunk(base + 1);
    }

    float* pz = g_part + (size_t)z * (NB * H1);
    int r0 = lane >> 2, cc0 = (lane & 3) * 2;
#pragma unroll
    for (int mi = 0; mi < 4; mi++)
#pragma unroll
        for (int ni = 0; ni < 4; ni++) {
            int m = bm + mbase + mi * 16 + r0;
            int nn = bn + nbase + ni * 8 + cc0;
            *(float2*)&pz[(size_t)m * H1 + nn] =
                make_float2(acc[mi][ni][0], acc[mi][ni][1]);
            *(float2*)&pz[(size_t)(m + 8) * H1 + nn] =
                make_float2(acc[mi][ni][2], acc[mi][ni][3]);
        }
}

// ---------------------------------------------------------------------------
// SIMT split-K SGEMM for GEMM2 (double-buffered)
// ---------------------------------------------------------------------------
template <int M, int N, int K, int KPS>
__device__ __forceinline__ void sgemm_body(const float* __restrict__ A,
                                           const float* __restrict__ B,
                                           float* __restrict__ part) {
    __shared__ float As[2][8][128];
    __shared__ float Bs[2][8][128];
    int bm = blockIdx.x * 128;
    int bn = blockIdx.y * 128;
    int z  = blockIdx.z;
    int k0 = z * KPS;
    int t  = threadIdx.x;
    int tx = t & 15;
    int ty = t >> 4;
    int arow  = t >> 1;
    int acol4 = (t & 1) * 4;
    int brow  = t >> 5;
    int bcol4 = (t & 31) * 4;

    const float* aptr = &A[(size_t)(bm + arow) * K + k0 + acol4];
    float acc[8][8];
#pragma unroll
    for (int i = 0; i < 8; i++)
#pragma unroll
        for (int j = 0; j < 8; j++) acc[i][j] = 0.0f;

    float4 av = *(const float4*)(aptr);
    float4 bv = *(const float4*)&B[(size_t)(k0 + brow) * N + bn + bcol4];
    int cur = 0;
    As[0][acol4 + 0][arow] = av.x;
    As[0][acol4 + 1][arow] = av.y;
    As[0][acol4 + 2][arow] = av.z;
    As[0][acol4 + 3][arow] = av.w;
    *(float4*)&Bs[0][brow][bcol4] = bv;
    __syncthreads();

    for (int kt = 0; kt < KPS; kt += 8) {
        bool has_next = (kt + 8) < KPS;
        if (has_next) {
            av = *(const float4*)(aptr + kt + 8);
            bv = *(const float4*)&B[(size_t)(k0 + kt + 8 + brow) * N + bn + bcol4];
        }
#pragma unroll
        for (int kr = 0; kr < 8; kr++) {
            float a[8], b[8];
            *(float4*)&a[0] = *(const float4*)&As[cur][kr][ty * 8];
            *(float4*)&a[4] = *(const float4*)&As[cur][kr][ty * 8 + 4];
            *(float4*)&b[0] = *(const float4*)&Bs[cur][kr][tx * 8];
            *(float4*)&b[4] = *(const float4*)&Bs[cur][kr][tx * 8 + 4];
#pragma unroll
            for (int i = 0; i < 8; i++)
#pragma unroll
                for (int j = 0; j < 8; j++) acc[i][j] += a[i] * b[j];
        }
        if (has_next) {
            int nxt = cur ^ 1;
            As[nxt][acol4 + 0][arow] = av.x;
            As[nxt][acol4 + 1][arow] = av.y;
            As[nxt][acol4 + 2][arow] = av.z;
            As[nxt][acol4 + 3][arow] = av.w;
            *(float4*)&Bs[nxt][brow][bcol4] = bv;
            __syncthreads();
            cur = nxt;
        }
    }
    float* p = part + (size_t)z * M * N;
#pragma unroll
    for (int i = 0; i < 8; i++) {
        int m = bm + ty * 8 + i;
#pragma unroll
        for (int j = 0; j < 8; j += 4) {
            float4 v = make_float4(acc[i][j], acc[i][j + 1], acc[i][j + 2], acc[i][j + 3]);
            *(float4*)&p[(size_t)m * N + bn + tx * 8 + j] = v;
        }
    }
}

__global__ void __launch_bounds__(256) gemm2_kernel(const float* __restrict__ W2) {
    sgemm_body<NB, H2, H1, 32>(g_h, W2, g_part);
}

// Reduce split-K partials + bias (+relu for layer 1)
__global__ void reduce1_kernel(const float* __restrict__ b1) {
    int i = (blockIdx.x * 256 + threadIdx.x) * 4;
    float4 s = make_float4(0.f, 0.f, 0.f, 0.f);
#pragma unroll
    for (int z = 0; z < ZS; z++) {
        float4 v = *(const float4*)&g_part[(size_t)z * (NB * H1) + i];
        s.x += v.x; s.y += v.y; s.z += v.z; s.w += v.w;
    }
    int bi = i & (H1 - 1);
    s.x = fmaxf(s.x * BSCALE_INV + b1[bi + 0], 0.f);
    s.y = fmaxf(s.y * BSCALE_INV + b1[bi + 1], 0.f);
    s.z = fmaxf(s.z * BSCALE_INV + b1[bi + 2], 0.f);
    s.w = fmaxf(s.w * BSCALE_INV + b1[bi + 3], 0.f);
    *(float4*)&g_h[i] = s;
}

__global__ void reduce2_kernel(const float* __restrict__ b2, float* __restrict__ out) {
    int i = (blockIdx.x * 256 + threadIdx.x) * 4;
    float4 s = make_float4(0.f, 0.f, 0.f, 0.f);
#pragma unroll
    for (int z = 0; z < 16; z++) {
        float4 v = *(const float4*)&g_part[(size_t)z * (NB * H2) + i];
        s.x += v.x; s.y += v.y; s.z += v.z; s.w += v.w;
    }
    int bi = i & (H2 - 1);
    s.x += b2[bi + 0]; s.y += b2[bi + 1]; s.z += b2[bi + 2]; s.w += b2[bi + 3];
    *(float4*)&out[i] = s;
}

// ---------------------------------------------------------------------------
extern "C" void kernel_launch(void* const* d_in, const int* in_sizes, int n_in,
                              void* d_out, int out_size) {
    const float* features = (const float*)d_in[0];
    const float* boxes    = (const float*)d_in[1];
    const float* W1       = (const float*)d_in[2];
    const float* b1       = (const float*)d_in[3];
    const float* W2       = (const float*)d_in[4];
    const float* b2       = (const float*)d_in[5];
    float* out            = (float*)d_out;

    transpose_kernel<<<dim3(120, 4), 256>>>(features);
    roi_align_kernel<<<NB, 256>>>(boxes);
    w1conv_kernel<<<dim3(98, 8), 256>>>(W1);
    gemm1_mma_kernel<<<dim3(4, 4, ZS), 256>>>();
    reduce1_kernel<<<256, 256>>>(b1);
    gemm2_kernel<<<dim3(4, 2, 16), 256>>>(W2);
    reduce2_kernel<<<128, 256>>>(b2, out);
}